// round 16
// baseline (speedup 1.0000x reference)
#include <cuda_runtime.h>
#include <stdint.h>

// Problem constants: images [64, 3, 512, 512] fp32, PATCH=8, TOP_K=512
#define BATCH   64
#define CH      3
#define HH      512
#define WW      512
#define PP      4096        // patches per image (64x64)
#define TOPK    512
#define NPATCH  (BATCH * PP)           // 262144

// Scratch (no allocations allowed in kernel_launch)
__device__ unsigned int g_bits[NPATCH];            // contrast as orderable uint bits
__device__ int          g_sel[BATCH * TOPK];       // selected patch idx per image

// ---------------------------------------------------------------------------
// Kernel 1: per-patch min/max -> contrast bits, FUSED with coalesced
// zero-fill of the whole output (copy later overwrites the selected 1/8).
// Read+write streams overlap on HBM: measured 63-64.5us vs ~63us serialized
// PLUS one launch gap and a full kernel's worth of store-only time saved.
// ---------------------------------------------------------------------------
__global__ void __launch_bounds__(256) contrast_zero_kernel(const float* __restrict__ in,
                                                            float* __restrict__ out) {
    int t    = threadIdx.x;
    int idx  = blockIdx.x * 256 + t;                // patch id in [0, NPATCH)
    int b    = idx >> 12;
    int pidx = idx & 4095;
    int ph   = pidx >> 6;
    int pw   = pidx & 63;

    const float4* in4 = reinterpret_cast<const float4*>(in);
    float mx = -1e30f, mn = 1e30f;

    #pragma unroll
    for (int c = 0; c < CH; c++) {
        #pragma unroll
        for (int py = 0; py < 8; py++) {
            int base = ((b * CH + c) * HH + ph * 8 + py) * (WW / 4) + pw * 2;
            float4 v0 = in4[base];
            float4 v1 = in4[base + 1];
            mx = fmaxf(mx, fmaxf(fmaxf(v0.x, v0.y), fmaxf(v0.z, v0.w)));
            mx = fmaxf(mx, fmaxf(fmaxf(v1.x, v1.y), fmaxf(v1.z, v1.w)));
            mn = fminf(mn, fminf(fminf(v0.x, v0.y), fminf(v0.z, v0.w)));
            mn = fminf(mn, fminf(fminf(v1.x, v1.y), fminf(v1.z, v1.w)));
        }
    }

    // Match JAX fp32 IEEE exactly: ((mx - mn) + eps) / (mx + mn), no contraction.
    float num = __fadd_rn(__fsub_rn(mx, mn), 1e-8f);
    float den = __fadd_rn(mx, mn);
    float ctr = __fdiv_rn(num, den);
    // ctr > 0 always -> positive-float bits order identically to float order.
    g_bits[idx] = __float_as_uint(ctr);

    // Coalesced zero-fill: this block covers its 256 patches' output region
    // (256 * 48 float4 = 192 KB, contiguous).
    float4* out4 = reinterpret_cast<float4*>(out);
    size_t zbase = (size_t)blockIdx.x * 256 * 48;
    const float4 z = make_float4(0.f, 0.f, 0.f, 0.f);
    #pragma unroll
    for (int i = 0; i < 48; i++)
        __stcs(&out4[zbase + (size_t)i * 256 + t], z);

#if __CUDA_ARCH__ >= 900
    cudaTriggerProgrammaticLaunchCompletion();
#endif
}

// ---------------------------------------------------------------------------
// Kernel 2: per-image exact top-512 via 4-pass 8-bit radix select, 1024
// threads per block. PDL secondary: gridsync before reading g_bits.
// Compacts the selected (512) index list. Tie-break matches jax.lax.top_k.
// ---------------------------------------------------------------------------
__global__ void __launch_bounds__(1024) select_kernel() {
    __shared__ unsigned int sv[PP];
    __shared__ unsigned int hist[256];
    __shared__ unsigned int sufs[256 + 1];
    __shared__ unsigned int s_thr;
    __shared__ int s_rank;
    __shared__ int wsum[32];
    __shared__ int wexc[32];

    int b = blockIdx.x;
    int t = threadIdx.x;
    int lane = t & 31;
    int warp = t >> 5;

    if (t == 0) { s_thr = 0u; s_rank = TOPK; sufs[256] = 0u; }

#if __CUDA_ARCH__ >= 900
    cudaGridDependencySynchronize();     // wait for contrast_zero completion
#endif

    // Coalesced load: 1024 threads x 1 uint4 = 4096 uints.
    {
        const uint4* src = reinterpret_cast<const uint4*>(&g_bits[b * PP]);
        reinterpret_cast<uint4*>(sv)[t] = src[t];
    }
    __syncthreads();

    unsigned int prefmask = 0u;
    #pragma unroll
    for (int pass = 3; pass >= 0; pass--) {
        int shift = pass * 8;
        if (t < 256) hist[t] = 0u;
        __syncthreads();
        unsigned int thr = s_thr;
        int rank = s_rank;

        // Warp-aggregated histogram (values are highly concentrated).
        #pragma unroll
        for (int i = 0; i < PP / 1024; i++) {
            unsigned int v = sv[t + i * 1024];
            bool act = ((v & prefmask) == thr);
            unsigned int actmask = __ballot_sync(0xFFFFFFFFu, act);
            if (act) {
                unsigned int bin = (v >> shift) & 255u;
                unsigned int peers = __match_any_sync(actmask, bin);
                if (lane == (__ffs(peers) - 1))
                    atomicAdd(&hist[bin], __popc(peers));
            }
        }
        __syncthreads();

        // Single-warp suffix sum: sufs[i] = hist[i] + ... + hist[255].
        if (warp == 0) {
            int base8 = lane * 8;
            unsigned int chunk = 0;
            #pragma unroll
            for (int k = 0; k < 8; k++) chunk += hist[base8 + k];
            unsigned int suf = chunk;
            #pragma unroll
            for (int off = 1; off < 32; off <<= 1) {
                unsigned int n = __shfl_down_sync(0xFFFFFFFFu, suf, off);
                if (lane + off < 32) suf += n;
            }
            unsigned int run = suf - chunk;      // bins strictly above my chunk
            #pragma unroll
            for (int k = 7; k >= 0; k--) {
                run += hist[base8 + k];
                sufs[base8 + k] = run;
            }
        }
        __syncthreads();

        // Exactly one thread's bin straddles the rank boundary.
        if (t < 256) {
            unsigned int above = sufs[t + 1];
            if (sufs[t] >= (unsigned)rank && above < (unsigned)rank) {
                s_thr  = thr | ((unsigned int)t << shift);
                s_rank = rank - (int)above;         // >= 1
            }
        }
        prefmask |= (0xFFu << shift);
        __syncthreads();
    }

    unsigned int thr = s_thr;       // exact 512th-largest value bits
    int need = s_rank;              // how many of the == thr values to include

    // Each thread owns a contiguous chunk of 4 patches.
    int base = t * 4;
    unsigned int v0 = sv[base + 0], v1 = sv[base + 1];
    unsigned int v2 = sv[base + 2], v3 = sv[base + 3];

    // ---- stable tie resolution: block scan of equal-to-threshold counts ----
    int local_eq = (v0 == thr) + (v1 == thr) + (v2 == thr) + (v3 == thr);
    int incl = local_eq;
    #pragma unroll
    for (int off = 1; off < 32; off <<= 1) {
        int n = __shfl_up_sync(0xFFFFFFFFu, incl, off);
        if (lane >= off) incl += n;
    }
    if (lane == 31) wsum[warp] = incl;
    __syncthreads();
    if (warp == 0) {
        int x = wsum[lane];
        int ix = x;
        #pragma unroll
        for (int off = 1; off < 32; off <<= 1) {
            int n = __shfl_up_sync(0xFFFFFFFFu, ix, off);
            if (lane >= off) ix += n;
        }
        wexc[lane] = ix - x;
    }
    __syncthreads();
    int run = wexc[warp] + (incl - local_eq);   // equals with smaller index

    // ---- build selection bits for my 4 patches ----
    unsigned int selbits = 0u;
    {
        unsigned int vv[4] = {v0, v1, v2, v3};
        #pragma unroll
        for (int k = 0; k < 4; k++) {
            bool m = false;
            if (vv[k] > thr) m = true;
            else if (vv[k] == thr) { m = (run < need); run++; }
            selbits |= (m ? 1u : 0u) << k;
        }
    }
    __syncthreads();

    // ---- compact selected indices via block scan ----
    int local_sel = __popc(selbits);
    int incl2 = local_sel;
    #pragma unroll
    for (int off = 1; off < 32; off <<= 1) {
        int n = __shfl_up_sync(0xFFFFFFFFu, incl2, off);
        if (lane >= off) incl2 += n;
    }
    if (lane == 31) wsum[warp] = incl2;
    __syncthreads();
    if (warp == 0) {
        int x = wsum[lane];
        int ix = x;
        #pragma unroll
        for (int off = 1; off < 32; off <<= 1) {
            int n = __shfl_up_sync(0xFFFFFFFFu, ix, off);
            if (lane >= off) ix += n;
        }
        wexc[lane] = ix - x;
    }
    __syncthreads();
    int pos = wexc[warp] + (incl2 - local_sel);

    int* sl = &g_sel[b * TOPK];
    #pragma unroll
    for (int k = 0; k < 4; k++) {
        if ((selbits >> k) & 1u)
            sl[pos++] = base + k;
    }
}

// ---------------------------------------------------------------------------
// Kernel 3: copy ONLY the selected patches. 16 patches per 384-thread block
// as two independent groups of 8 (48 threads/patch, MLP=2). PDL secondary of
// select; gridsync before reading g_sel (also orders after the zero stores
// via the grid-completion chain).
// ---------------------------------------------------------------------------
__global__ void __launch_bounds__(384) copy_kernel(const float* __restrict__ in,
                                                   float* __restrict__ out) {
#if __CUDA_ARCH__ >= 900
    cudaGridDependencySynchronize();     // select grid complete (g_sel final)
#endif
    int t   = threadIdx.x;
    int lp  = t / 48;                        // 0..7 local patch in group
    int f4  = t - lp * 48;                   // 0..47 float4 slot within patch
    int c   = f4 >> 4;                       // 0..2
    int rem = f4 & 15;
    int py  = rem >> 1;                      // 0..7
    int q   = rem & 1;                       // half-row (4 floats)

    const float4* in4 = reinterpret_cast<const float4*>(in);
    float4* out4 = reinterpret_cast<float4*>(out);

    int j0 = blockIdx.x * 16 + lp;           // dense selected index
    int b0 = j0 >> 9;                        // 512 selected per image
    int p0 = g_sel[j0];
    int j1 = j0 + 8;
    int b1 = j1 >> 9;
    int p1 = g_sel[j1];

    int ia0 = ((b0 * CH + c) * HH + (p0 >> 6) * 8 + py) * (WW / 4) + (p0 & 63) * 2 + q;
    int ia1 = ((b1 * CH + c) * HH + (p1 >> 6) * 8 + py) * (WW / 4) + (p1 & 63) * 2 + q;

    float4 v0 = __ldcs(&in4[ia0]);           // two independent gathers in flight
    float4 v1 = __ldcs(&in4[ia1]);

    __stcs(&out4[((size_t)b0 * PP + p0) * 48 + f4], v0);
    __stcs(&out4[((size_t)b1 * PP + p1) * 48 + f4], v1);
}

// ---------------------------------------------------------------------------
static inline void launch_pdl(void* fn, dim3 grid, dim3 block, void** args) {
    cudaLaunchConfig_t cfg = {};
    cfg.gridDim  = grid;
    cfg.blockDim = block;
    cudaLaunchAttribute attr[1];
    attr[0].id = cudaLaunchAttributeProgrammaticStreamSerialization;
    attr[0].val.programmaticStreamSerializationAllowed = 1;
    cfg.attrs = attr;
    cfg.numAttrs = 1;
    cudaLaunchKernelExC(&cfg, fn, args);
}

extern "C" void kernel_launch(void* const* d_in, const int* in_sizes, int n_in,
                              void* d_out, int out_size) {
    const float* in  = (const float*)d_in[0];
    float*       out = (float*)d_out;

    {   // fused contrast + zero-fill (read+write streams overlap on HBM)
        void* a0 = (void*)in;
        void* a1 = (void*)out;
        void* args[] = { &a0, &a1 };
        contrast_zero_kernel<<<NPATCH / 256, 256>>>(in, out);
        (void)args;
    }
    {   // select: PDL secondary of contrast_zero (gridsync inside)
        void* args[] = {};
        launch_pdl((void*)select_kernel, dim3(BATCH), dim3(1024), args);
    }
    {   // copy: PDL secondary of select (gridsync inside)
        void* a0 = (void*)in;
        void* a1 = (void*)out;
        void* args[] = { &a0, &a1 };
        launch_pdl((void*)copy_kernel, dim3((BATCH * TOPK) / 16), dim3(384), args);
    }
}

// round 17
// speedup vs baseline: 1.1197x; 1.1197x over previous
#include <cuda_runtime.h>
#include <stdint.h>

// Problem constants: images [64, 3, 512, 512] fp32, PATCH=8, TOP_K=512
#define BATCH   64
#define CH      3
#define HH      512
#define WW      512
#define PP      4096        // patches per image (64x64)
#define TOPK    512
#define NPATCH  (BATCH * PP)           // 262144

// Scratch (no allocations allowed in kernel_launch)
__device__ unsigned int  g_bits[NPATCH];           // contrast as orderable uint bits
__device__ int           g_sel[BATCH * TOPK];      // selected patch idx per image
__device__ unsigned char g_mask[NPATCH];           // 1 = selected

// ---------------------------------------------------------------------------
// Kernel 1: per-patch min/max -> contrast bits. One thread per patch.
// Caching loads on purpose: leaves the input tail resident in L2 for the
// copy kernel's gather.
// ---------------------------------------------------------------------------
__global__ void __launch_bounds__(256) contrast_kernel(const float* __restrict__ in) {
    int idx  = blockIdx.x * 256 + threadIdx.x;      // patch id in [0, NPATCH)
    int b    = idx >> 12;
    int pidx = idx & 4095;
    int ph   = pidx >> 6;
    int pw   = pidx & 63;

    const float4* in4 = reinterpret_cast<const float4*>(in);
    float mx = -1e30f, mn = 1e30f;

    #pragma unroll
    for (int c = 0; c < CH; c++) {
        #pragma unroll
        for (int py = 0; py < 8; py++) {
            int base = ((b * CH + c) * HH + ph * 8 + py) * (WW / 4) + pw * 2;
            float4 v0 = in4[base];
            float4 v1 = in4[base + 1];
            mx = fmaxf(mx, fmaxf(fmaxf(v0.x, v0.y), fmaxf(v0.z, v0.w)));
            mx = fmaxf(mx, fmaxf(fmaxf(v1.x, v1.y), fmaxf(v1.z, v1.w)));
            mn = fminf(mn, fminf(fminf(v0.x, v0.y), fminf(v0.z, v0.w)));
            mn = fminf(mn, fminf(fminf(v1.x, v1.y), fminf(v1.z, v1.w)));
        }
    }

    // Match JAX fp32 IEEE exactly: ((mx - mn) + eps) / (mx + mn), no contraction.
    float num = __fadd_rn(__fsub_rn(mx, mn), 1e-8f);
    float den = __fadd_rn(mx, mn);
    float ctr = __fdiv_rn(num, den);
    // ctr > 0 always -> positive-float bits order identically to float order.
    g_bits[idx] = __float_as_uint(ctr);

#if __CUDA_ARCH__ >= 900
    cudaTriggerProgrammaticLaunchCompletion();
#endif
}

// ---------------------------------------------------------------------------
// Kernel 2: per-image exact top-512 via 4-pass 8-bit radix select, 1024
// threads per block. PDL secondary: gridsync before reading g_bits.
// Emits dense selected list + per-patch mask bytes.
// Tie-break matches jax.lax.top_k (lowest index first).
// ---------------------------------------------------------------------------
__global__ void __launch_bounds__(1024) select_kernel() {
    __shared__ unsigned int sv[PP];
    __shared__ unsigned int hist[256];
    __shared__ unsigned int sufs[256 + 1];
    __shared__ unsigned int s_thr;
    __shared__ int s_rank;
    __shared__ int wsum[32];
    __shared__ int wexc[32];

    int b = blockIdx.x;
    int t = threadIdx.x;
    int lane = t & 31;
    int warp = t >> 5;

    if (t == 0) { s_thr = 0u; s_rank = TOPK; sufs[256] = 0u; }

#if __CUDA_ARCH__ >= 900
    cudaGridDependencySynchronize();     // wait for contrast grid completion
#endif

    // Coalesced load: 1024 threads x 1 uint4 = 4096 uints.
    {
        const uint4* src = reinterpret_cast<const uint4*>(&g_bits[b * PP]);
        reinterpret_cast<uint4*>(sv)[t] = src[t];
    }
    __syncthreads();

    unsigned int prefmask = 0u;
    #pragma unroll
    for (int pass = 3; pass >= 0; pass--) {
        int shift = pass * 8;
        if (t < 256) hist[t] = 0u;
        __syncthreads();
        unsigned int thr = s_thr;
        int rank = s_rank;

        // Warp-aggregated histogram (values are highly concentrated).
        #pragma unroll
        for (int i = 0; i < PP / 1024; i++) {
            unsigned int v = sv[t + i * 1024];
            bool act = ((v & prefmask) == thr);
            unsigned int actmask = __ballot_sync(0xFFFFFFFFu, act);
            if (act) {
                unsigned int bin = (v >> shift) & 255u;
                unsigned int peers = __match_any_sync(actmask, bin);
                if (lane == (__ffs(peers) - 1))
                    atomicAdd(&hist[bin], __popc(peers));
            }
        }
        __syncthreads();

        // Single-warp suffix sum: sufs[i] = hist[i] + ... + hist[255].
        if (warp == 0) {
            int base8 = lane * 8;
            unsigned int chunk = 0;
            #pragma unroll
            for (int k = 0; k < 8; k++) chunk += hist[base8 + k];
            unsigned int suf = chunk;
            #pragma unroll
            for (int off = 1; off < 32; off <<= 1) {
                unsigned int n = __shfl_down_sync(0xFFFFFFFFu, suf, off);
                if (lane + off < 32) suf += n;
            }
            unsigned int run = suf - chunk;      // bins strictly above my chunk
            #pragma unroll
            for (int k = 7; k >= 0; k--) {
                run += hist[base8 + k];
                sufs[base8 + k] = run;
            }
        }
        __syncthreads();

        // Exactly one thread's bin straddles the rank boundary.
        if (t < 256) {
            unsigned int above = sufs[t + 1];
            if (sufs[t] >= (unsigned)rank && above < (unsigned)rank) {
                s_thr  = thr | ((unsigned int)t << shift);
                s_rank = rank - (int)above;         // >= 1
            }
        }
        prefmask |= (0xFFu << shift);
        __syncthreads();
    }

    unsigned int thr = s_thr;       // exact 512th-largest value bits
    int need = s_rank;              // how many of the == thr values to include

    // Each thread owns a contiguous chunk of 4 patches.
    int base = t * 4;
    unsigned int v0 = sv[base + 0], v1 = sv[base + 1];
    unsigned int v2 = sv[base + 2], v3 = sv[base + 3];

    // ---- stable tie resolution: block scan of equal-to-threshold counts ----
    int local_eq = (v0 == thr) + (v1 == thr) + (v2 == thr) + (v3 == thr);
    int incl = local_eq;
    #pragma unroll
    for (int off = 1; off < 32; off <<= 1) {
        int n = __shfl_up_sync(0xFFFFFFFFu, incl, off);
        if (lane >= off) incl += n;
    }
    if (lane == 31) wsum[warp] = incl;
    __syncthreads();
    if (warp == 0) {
        int x = wsum[lane];
        int ix = x;
        #pragma unroll
        for (int off = 1; off < 32; off <<= 1) {
            int n = __shfl_up_sync(0xFFFFFFFFu, ix, off);
            if (lane >= off) ix += n;
        }
        wexc[lane] = ix - x;
    }
    __syncthreads();
    int run = wexc[warp] + (incl - local_eq);   // equals with smaller index

    // ---- build selection bits for my 4 patches + write mask bytes ----
    unsigned int selbits = 0u;
    {
        unsigned int vv[4] = {v0, v1, v2, v3};
        uchar4 mb;
        unsigned char* mc = &mb.x;
        #pragma unroll
        for (int k = 0; k < 4; k++) {
            bool m = false;
            if (vv[k] > thr) m = true;
            else if (vv[k] == thr) { m = (run < need); run++; }
            selbits |= (m ? 1u : 0u) << k;
            mc[k] = m ? 1 : 0;
        }
        *reinterpret_cast<uchar4*>(&g_mask[b * PP + base]) = mb;
    }
    __syncthreads();

    // ---- compact selected indices via block scan ----
    int local_sel = __popc(selbits);
    int incl2 = local_sel;
    #pragma unroll
    for (int off = 1; off < 32; off <<= 1) {
        int n = __shfl_up_sync(0xFFFFFFFFu, incl2, off);
        if (lane >= off) incl2 += n;
    }
    if (lane == 31) wsum[warp] = incl2;
    __syncthreads();
    if (warp == 0) {
        int x = wsum[lane];
        int ix = x;
        #pragma unroll
        for (int off = 1; off < 32; off <<= 1) {
            int n = __shfl_up_sync(0xFFFFFFFFu, ix, off);
            if (lane >= off) ix += n;
        }
        wexc[lane] = ix - x;
    }
    __syncthreads();
    int pos = wexc[warp] + (incl2 - local_sel);

    int* sl = &g_sel[b * TOPK];
    #pragma unroll
    for (int k = 0; k < 4; k++) {
        if ((selbits >> k) & 1u)
            sl[pos++] = base + k;
    }
}

// ---------------------------------------------------------------------------
// Kernel 3 (runs BEFORE zero): copy the selected patches. Scheduled right
// after select so the gather hits the input tail still resident in L2 from
// contrast (caching loads, not __ldcs). gridsync on select, THEN fire the
// PDL trigger: the zero kernel launched off this trigger needs only select's
// g_mask, so it can overlap all of copy's execution.
// ---------------------------------------------------------------------------
__global__ void __launch_bounds__(384) copy_kernel(const float* __restrict__ in,
                                                   float* __restrict__ out) {
#if __CUDA_ARCH__ >= 900
    cudaGridDependencySynchronize();              // select complete (g_sel/g_mask final)
    cudaTriggerProgrammaticLaunchCompletion();    // zero may launch now
#endif
    int t   = threadIdx.x;
    int lp  = t / 48;                        // 0..7 local patch in group
    int f4  = t - lp * 48;                   // 0..47 float4 slot within patch
    int c   = f4 >> 4;                       // 0..2
    int rem = f4 & 15;
    int py  = rem >> 1;                      // 0..7
    int q   = rem & 1;                       // half-row (4 floats)

    const float4* in4 = reinterpret_cast<const float4*>(in);
    float4* out4 = reinterpret_cast<float4*>(out);

    int j0 = blockIdx.x * 16 + lp;           // dense selected index
    int b0 = j0 >> 9;                        // 512 selected per image
    int p0 = g_sel[j0];
    int j1 = j0 + 8;
    int b1 = j1 >> 9;
    int p1 = g_sel[j1];

    int ia0 = ((b0 * CH + c) * HH + (p0 >> 6) * 8 + py) * (WW / 4) + (p0 & 63) * 2 + q;
    int ia1 = ((b1 * CH + c) * HH + (p1 >> 6) * 8 + py) * (WW / 4) + (p1 & 63) * 2 + q;

    float4 v0 = in4[ia0];                    // caching loads -> L2 reuse
    float4 v1 = in4[ia1];

    __stcs(&out4[((size_t)b0 * PP + p0) * 48 + f4], v0);
    __stcs(&out4[((size_t)b1 * PP + p1) * 48 + f4], v1);
}

// ---------------------------------------------------------------------------
// Kernel 4: zero ONLY the unselected patches (mask-predicated, linear
// addressing -> coalesced; 176MB). PDL secondary of copy with NO gridsync:
// copy fires its trigger only after select's grid completed, so g_mask is
// final and visible; zero's writes are disjoint from copy's (complement),
// so full overlap with copy is safe.
// ---------------------------------------------------------------------------
__global__ void __launch_bounds__(256) zero_kernel(float* __restrict__ out) {
    __shared__ unsigned char m[64];
    int t = threadIdx.x;
    if (t < 64) m[t] = g_mask[blockIdx.x * 64 + t];
    __syncthreads();

    float4* out4 = reinterpret_cast<float4*>(out);
    size_t base = (size_t)blockIdx.x * 3072;
    const float4 z = make_float4(0.f, 0.f, 0.f, 0.f);
    #pragma unroll
    for (int i = 0; i < 12; i++) {
        int fl = i * 256 + t;               // local float4 idx [0, 3072)
        if (!m[fl / 48])                    // patch-local mask
            __stcs(&out4[base + fl], z);
    }
}

// ---------------------------------------------------------------------------
static inline void launch_pdl(void* fn, dim3 grid, dim3 block, void** args) {
    cudaLaunchConfig_t cfg = {};
    cfg.gridDim  = grid;
    cfg.blockDim = block;
    cudaLaunchAttribute attr[1];
    attr[0].id = cudaLaunchAttributeProgrammaticStreamSerialization;
    attr[0].val.programmaticStreamSerializationAllowed = 1;
    cfg.attrs = attr;
    cfg.numAttrs = 1;
    cudaLaunchKernelExC(&cfg, fn, args);
}

extern "C" void kernel_launch(void* const* d_in, const int* in_sizes, int n_in,
                              void* d_out, int out_size) {
    const float* in  = (const float*)d_in[0];
    float*       out = (float*)d_out;

    contrast_kernel<<<NPATCH / 256, 256>>>(in);

    {   // select: PDL secondary of contrast (gridsync inside)
        void* args[] = {};
        launch_pdl((void*)select_kernel, dim3(BATCH), dim3(1024), args);
    }
    {   // copy: PDL secondary of select; runs first for L2 input reuse
        void* a0 = (void*)in;
        void* a1 = (void*)out;
        void* args[] = { &a0, &a1 };
        launch_pdl((void*)copy_kernel, dim3((BATCH * TOPK) / 16), dim3(384), args);
    }
    {   // zero: PDL secondary of copy (trigger fired after select completed);
        // disjoint writes -> overlaps copy fully.
        void* a0 = (void*)out;
        void* args[] = { &a0 };
        launch_pdl((void*)zero_kernel, dim3(NPATCH / 64), dim3(256), args);
    }
}